// round 8
// baseline (speedup 1.0000x reference)
#include <cuda_runtime.h>
#include <cuda_bf16.h>
#include <cstdint>

typedef unsigned long long ull;

#define NPTS  10000
#define NPAD  10016
#define DDIM  3072

__device__ __align__(16) float g_cp[4 * 16 * NPAD];
__device__ __align__(16) float g_ip[4 * NPAD];
__device__ __align__(16) float g_lg[16 * NPAD];
__device__ __align__(16) float g_w [NPAD * 16];
__device__ __align__(16) float g_mp[4 * 16 * DDIM];
__device__ __align__(16) float g_xt[DDIM * 16];
__device__ float g_pmax[16 * 8];
__device__ float g_psum[16 * 128];
__device__ float g_c[4];

__device__ __forceinline__ ull dup2(float v) {
    ull r; asm("mov.b64 %0, {%1, %1};" : "=l"(r) : "f"(v)); return r;
}
__device__ __forceinline__ void fma2(ull& d, ull a, ull b) {
    asm("fma.rn.f32x2 %0, %1, %2, %0;" : "+l"(d) : "l"(a), "l"(b));
}
__device__ __forceinline__ void unpack2(ull v, float& lo, float& hi) {
    asm("mov.b64 {%0, %1}, %2;" : "=f"(lo), "=f"(hi) : "l"(v));
}

__global__ void kconst(const float* __restrict__ sval) {
    if (threadIdx.x == 0) {
        float s = sval[0];
        float at = sqrtf(1.f - s);
        g_c[0] = at; g_c[1] = s;
        g_c[2] = at / s;
        g_c[3] = -(at * at) / (2.f * s);
    }
}

__global__ __launch_bounds__(256) void ktr(const float* __restrict__ x, int off) {
    int i = off + blockIdx.x * 256 + threadIdx.x;
    if (i < DDIM * 16) {
        int b = i & 15, k = i >> 4;
        g_xt[i] = x[b * DDIM + k];
    }
}

// ---- k1: 628 CTAs x 256. tile=c>>2 (64 n), kq=c&3 (768 k), 24 chunks of 32 k.
// Thread (n_l=t&31, kp=t>>5): rows n_l & n_l+32, 4 k per chunk. x-LDS amortized 2x.
__global__ __launch_bounds__(256) void k1(const float* __restrict__ img) {
    __shared__ float sbuf[2][64 * 32];
    __shared__ float xts[2][32 * 16];
    __shared__ float2 red2[512];

    const int t = threadIdx.x, c = blockIdx.x;
    const int tile = c >> 2, kq = c & 3;
    const int n0 = tile * 64, k0 = kq * 768;
    const int n_l = t & 31, kp = t >> 5;
    const int lrow = t >> 3, lc4 = t & 7;
    const int rA = n0 + lrow, rB = n0 + lrow + 32;
    const int swA = lrow * 32 + ((lc4 ^ (lrow & 7)) << 2);
    const int swB = (lrow + 32) * 32 + ((lc4 ^ (lrow & 7)) << 2);
    const float4 z4 = make_float4(0.f, 0.f, 0.f, 0.f);

    ull accA[8], accB[8];
#pragma unroll
    for (int j = 0; j < 8; j++) { accA[j] = 0ULL; accB[j] = 0ULL; }
    float isqA = 0.f, isqB = 0.f;

    float4 pA, pB, pX = z4;
    {
        pA = (rA < NPTS) ? *(const float4*)(img + (size_t)rA * DDIM + k0 + lc4 * 4) : z4;
        pB = (rB < NPTS) ? *(const float4*)(img + (size_t)rB * DDIM + k0 + lc4 * 4) : z4;
        if (t < 128) pX = ((const float4*)(g_xt + (size_t)k0 * 16))[t];
        *(float4*)&sbuf[0][swA] = pA;
        *(float4*)&sbuf[0][swB] = pB;
        if (t < 128) ((float4*)xts[0])[t] = pX;
    }
    __syncthreads();

    const int p0 = n_l * 32 + ((kp ^ (n_l & 7)) << 2);
    const int p1 = (n_l + 32) * 32 + ((kp ^ (n_l & 7)) << 2);
    const int xo = kp * 4 * 16;

    for (int ch = 0; ch < 24; ch++) {
        const int s = ch & 1;
        if (ch + 1 < 24) {
            int kk0 = k0 + (ch + 1) * 32;
            pA = (rA < NPTS) ? *(const float4*)(img + (size_t)rA * DDIM + kk0 + lc4 * 4) : z4;
            pB = (rB < NPTS) ? *(const float4*)(img + (size_t)rB * DDIM + kk0 + lc4 * 4) : z4;
            if (t < 128) pX = ((const float4*)(g_xt + (size_t)kk0 * 16))[t];
        }
        const float* sb = sbuf[s];
        const float* xt = xts[s];
        float4 v0 = *(const float4*)&sb[p0];
        float4 v1 = *(const float4*)&sb[p1];
#pragma unroll
        for (int kk = 0; kk < 4; kk++) {
            float fA = (&v0.x)[kk], fB = (&v1.x)[kk];
            isqA = fmaf(fA, fA, isqA);
            isqB = fmaf(fB, fB, isqB);
            ull dA = dup2(fA), dB = dup2(fB);
            const ulonglong2* xr = (const ulonglong2*)(xt + xo + kk * 16);
#pragma unroll
            for (int j = 0; j < 4; j++) {
                ulonglong2 u = xr[j];
                fma2(accA[2 * j],     u.x, dA);
                fma2(accA[2 * j + 1], u.y, dA);
                fma2(accB[2 * j],     u.x, dB);
                fma2(accB[2 * j + 1], u.y, dB);
            }
        }
        __syncthreads();
        if (ch + 1 < 24) {
            *(float4*)&sbuf[s ^ 1][swA] = pA;
            *(float4*)&sbuf[s ^ 1][swB] = pB;
            if (t < 128) ((float4*)xts[s ^ 1])[t] = pX;
            __syncthreads();
        }
    }

    // epilogue: reduce over kp (8) for both row halves
#pragma unroll 1
    for (int bp = 0; bp < 8; bp++) {
        __syncthreads();
        float lo, hi;
        unpack2(accA[bp], lo, hi); red2[kp * 32 + n_l] = make_float2(lo, hi);
        unpack2(accB[bp], lo, hi); red2[256 + kp * 32 + n_l] = make_float2(lo, hi);
        __syncthreads();
        if (t < 64) {
            int base = (t < 32) ? 0 : 256;
            int r = t & 31;
            float sx = 0.f, sy = 0.f;
#pragma unroll
            for (int q = 0; q < 8; q++) {
                float2 v = red2[base + q * 32 + r];
                sx += v.x; sy += v.y;
            }
            int n = n0 + t;
            if (n < NPTS) {
                g_cp[(kq * 16 + 2 * bp) * NPAD + n] = sx;
                g_cp[(kq * 16 + 2 * bp + 1) * NPAD + n] = sy;
            }
        }
    }
    __syncthreads();
    ((float*)red2)[kp * 32 + n_l] = isqA;
    ((float*)red2)[256 + kp * 32 + n_l] = isqB;
    __syncthreads();
    if (t < 64) {
        int base = (t < 32) ? 0 : 256;
        int r = t & 31;
        const float* rf = (const float*)red2;
        float s = 0.f;
#pragma unroll
        for (int q = 0; q < 8; q++) s += rf[base + q * 32 + r];
        int n = n0 + t;
        if (n < NPTS) g_ip[kq * NPAD + n] = s;
    }
}

__global__ __launch_bounds__(256) void s1() {
    const int t = threadIdx.x, c = blockIdx.x;
    const int b = c >> 3, seg = c & 7;
    const float c1 = g_c[2], c2 = g_c[3];
    const int nbase = seg * 1252;
    const int nend = min(nbase + 1252, NPTS);
    float m = -1e30f;
    for (int i = nbase + t; i < nend; i += 256) {
        float cr = g_cp[b * NPAD + i] + g_cp[(16 + b) * NPAD + i]
                 + g_cp[(32 + b) * NPAD + i] + g_cp[(48 + b) * NPAD + i];
        float qq = g_ip[i] + g_ip[NPAD + i] + g_ip[2 * NPAD + i] + g_ip[3 * NPAD + i];
        float lg = fmaf(c1, cr, c2 * qq);
        g_lg[b * NPAD + i] = lg;
        m = fmaxf(m, lg);
    }
    __shared__ float wm[8];
    for (int o = 16; o; o >>= 1) m = fmaxf(m, __shfl_xor_sync(0xffffffffu, m, o));
    if ((t & 31) == 0) wm[t >> 5] = m;
    __syncthreads();
    if (t == 0) {
        float v = wm[0];
        for (int w = 1; w < 8; w++) v = fmaxf(v, wm[w]);
        g_pmax[c] = v;
    }
}

__global__ __launch_bounds__(256) void s3() {
    const int t = threadIdx.x, c = blockIdx.x;
    const int bb = t & 15, nn = t >> 4;
    const float L2E = 1.44269504088896340736f;
    float M = g_pmax[bb * 8];
#pragma unroll
    for (int s = 1; s < 8; s++) M = fmaxf(M, g_pmax[bb * 8 + s]);
    const int base = c * 79;
    float sum = 0.f;
#pragma unroll
    for (int r = 0; r < 5; r++) {
        int n = base + nn + 16 * r;
        if (n < base + 79 && n < NPTS) {
            float e = exp2f((g_lg[bb * NPAD + n] - M) * L2E);
            g_w[n * 16 + bb] = e;
            sum += e;
        }
    }
    sum += __shfl_xor_sync(0xffffffffu, sum, 16);
    __shared__ float sm[8 * 16];
    if ((t & 31) < 16) sm[(t >> 5) * 16 + bb] = sum;
    __syncthreads();
    if (t < 16) {
        float s = 0.f;
        for (int w = 0; w < 8; w++) s += sm[w * 16 + t];
        g_psum[t * 128 + c] = s;
    }
}

__global__ __launch_bounds__(256) void k3(const float* __restrict__ img) {
    __shared__ float red[256 * 8];
    const int t = threadIdx.x, c = blockIdx.x;
    const int dtile = c >> 2, quarter = c & 3;
    const int dt = t & 7, bh = (t >> 3) & 1, p = t >> 4;
    const int dbase = dtile * 32 + dt * 4;
    const int q0 = quarter * 2500;

    ull acc[4][4];
#pragma unroll
    for (int i = 0; i < 4; i++)
#pragma unroll
        for (int j = 0; j < 4; j++) acc[i][j] = 0ULL;

#pragma unroll 2
    for (int j = 0; j < 156; j += 2) {
        int n1 = q0 + p + 16 * j, n2 = n1 + 16;
        float4 i1 = *(const float4*)(img + (size_t)n1 * DDIM + dbase);
        float4 i2 = *(const float4*)(img + (size_t)n2 * DDIM + dbase);
        ulonglong2 wa1 = *(const ulonglong2*)(g_w + (size_t)n1 * 16 + bh * 8);
        ulonglong2 wb1 = *(const ulonglong2*)(g_w + (size_t)n1 * 16 + bh * 8 + 4);
        ulonglong2 wa2 = *(const ulonglong2*)(g_w + (size_t)n2 * 16 + bh * 8);
        ulonglong2 wb2 = *(const ulonglong2*)(g_w + (size_t)n2 * 16 + bh * 8 + 4);
#pragma unroll
        for (int d = 0; d < 4; d++) {
            ull dv = dup2((&i1.x)[d]);
            fma2(acc[0][d], wa1.x, dv);
            fma2(acc[1][d], wa1.y, dv);
            fma2(acc[2][d], wb1.x, dv);
            fma2(acc[3][d], wb1.y, dv);
        }
#pragma unroll
        for (int d = 0; d < 4; d++) {
            ull dv = dup2((&i2.x)[d]);
            fma2(acc[0][d], wa2.x, dv);
            fma2(acc[1][d], wa2.y, dv);
            fma2(acc[2][d], wb2.x, dv);
            fma2(acc[3][d], wb2.y, dv);
        }
    }
    if (p < 4) {
        int n = q0 + 2496 + p;
        float4 i1 = *(const float4*)(img + (size_t)n * DDIM + dbase);
        ulonglong2 wa = *(const ulonglong2*)(g_w + (size_t)n * 16 + bh * 8);
        ulonglong2 wb = *(const ulonglong2*)(g_w + (size_t)n * 16 + bh * 8 + 4);
#pragma unroll
        for (int d = 0; d < 4; d++) {
            ull dv = dup2((&i1.x)[d]);
            fma2(acc[0][d], wa.x, dv);
            fma2(acc[1][d], wa.y, dv);
            fma2(acc[2][d], wb.x, dv);
            fma2(acc[3][d], wb.y, dv);
        }
    }

#pragma unroll 1
    for (int bp = 0; bp < 4; bp++) {
        __syncthreads();
#pragma unroll
        for (int d = 0; d < 4; d++) {
            float lo, hi; unpack2(acc[bp][d], lo, hi);
            red[t * 8 + 2 * d] = lo;
            red[t * 8 + 2 * d + 1] = hi;
        }
        __syncthreads();
        if (t < 128) {
            int h = t & 1, d = (t >> 1) & 3, dtw = (t >> 3) & 7, bhw = t >> 6;
            float s = 0.f;
#pragma unroll
            for (int p2 = 0; p2 < 16; p2++)
                s += red[(dtw + bhw * 8 + p2 * 16) * 8 + 2 * d + h];
            int b = bhw * 8 + bp * 2 + h;
            g_mp[(quarter * 16 + b) * DDIM + dtile * 32 + dtw * 4 + d] = s;
        }
    }
}

__global__ __launch_bounds__(256) void k4(const float* __restrict__ x,
                                          float* __restrict__ out) {
    const int t = threadIdx.x, c = blockIdx.x;
    const int blo = (c * 1024) / DDIM;
    const int bhi = ((c + 1) * 1024 - 1) / DDIM;
    __shared__ float wsum[8];
    __shared__ float invs[2];
    {
        int myb = (t < 128) ? blo : bhi;
        float s = g_psum[myb * 128 + (t & 127)];
        for (int o = 16; o; o >>= 1) s += __shfl_xor_sync(0xffffffffu, s, o);
        if ((t & 31) == 0) wsum[t >> 5] = s;
    }
    __syncthreads();
    if (t == 0)   invs[0] = 1.f / (wsum[0] + wsum[1] + wsum[2] + wsum[3]);
    if (t == 128) invs[1] = 1.f / (wsum[4] + wsum[5] + wsum[6] + wsum[7]);
    __syncthreads();

    const float at = g_c[0], bt2 = g_c[1];
    int i = (c * 256 + t) * 4;
    int b = i / DDIM;
    int d = i - b * DDIM;
    float inv = (b == blo) ? invs[0] : invs[1];
    float4 m0 = *(const float4*)(g_mp + (size_t)b * DDIM + d);
    float4 m1 = *(const float4*)(g_mp + (size_t)(16 + b) * DDIM + d);
    float4 m2 = *(const float4*)(g_mp + (size_t)(32 + b) * DDIM + d);
    float4 m3 = *(const float4*)(g_mp + (size_t)(48 + b) * DDIM + d);
    float4 xv = *(const float4*)(x + i);
    float sc = at * inv / bt2;
    float4 o;
    o.x = sc * (m0.x + m1.x + m2.x + m3.x) - xv.x / bt2;
    o.y = sc * (m0.y + m1.y + m2.y + m3.y) - xv.y / bt2;
    o.z = sc * (m0.z + m1.z + m2.z + m3.z) - xv.z / bt2;
    o.w = sc * (m0.w + m1.w + m2.w + m3.w) - xv.w / bt2;
    *(float4*)(out + i) = o;
}

extern "C" void kernel_launch(void* const* d_in, const int* in_sizes, int n_in,
                              void* d_out, int out_size) {
    const float* x    = (const float*)d_in[0];
    const float* img  = (const float*)d_in[1];
    const float* sval = (const float*)d_in[2];
    float* out = (float*)d_out;

    kconst<<<1, 32>>>(sval);
    ktr<<<96, 256>>>(x, 0);
    ktr<<<96, 256>>>(x, 24576);
    k1<<<628, 256>>>(img);     // capture index 3
    s1<<<128, 256>>>();
    s3<<<128, 256>>>();
    k3<<<384, 256>>>(img);
    k4<<<48, 256>>>(x, out);
}

// round 9
// speedup vs baseline: 1.0947x; 1.0947x over previous
#include <cuda_runtime.h>
#include <cstdint>

typedef unsigned long long ull;

#define NPTS  10000
#define NPAD  10016
#define DDIM  3072

__device__ __align__(16) float g_cp[4 * 16 * NPAD];
__device__ __align__(16) float g_ip[4 * NPAD];
__device__ __align__(16) float g_lg[16 * NPAD];
__device__ __align__(16) float g_w [NPAD * 16];
__device__ __align__(16) float g_mp[4 * 16 * DDIM];
__device__ __align__(16) float g_xt[DDIM * 16];
__device__ float g_pmax[16 * 8];
__device__ float g_psum[16 * 128];
__device__ float g_c[4];
__device__ unsigned g_barc;

__device__ __forceinline__ ull dup2(float v) {
    ull r; asm("mov.b64 %0, {%1, %1};" : "=l"(r) : "f"(v)); return r;
}
__device__ __forceinline__ void fma2(ull& d, ull a, ull b) {
    asm("fma.rn.f32x2 %0, %1, %2, %0;" : "+l"(d) : "l"(a), "l"(b));
}
__device__ __forceinline__ void unpack2(ull v, float& lo, float& hi) {
    asm("mov.b64 {%0, %1}, %2;" : "=f"(lo), "=f"(hi) : "l"(v));
}

// ---- L0: transpose x + constants + barrier reset (192 CTAs) ----
__global__ __launch_bounds__(256) void ktrc(const float* __restrict__ x,
                                            const float* __restrict__ sval) {
    int i = blockIdx.x * 256 + threadIdx.x;
    if (i < DDIM * 16) {
        int b = i & 15, k = i >> 4;
        g_xt[i] = x[b * DDIM + k];
    }
    if (i == 0) {
        float s = sval[0];
        float at = sqrtf(1.f - s);
        g_c[0] = at; g_c[1] = s;
        g_c[2] = at / s;
        g_c[3] = -(at * at) / (2.f * s);
        g_barc = 0u;
    }
}

// ---- L1: k1 (R4-proven variant): 628 CTAs x 256 ----
__global__ __launch_bounds__(256) void k1(const float* __restrict__ img) {
    __shared__ float sbuf[2][64 * 32];
    __shared__ float xts[2][32 * 16];
    __shared__ float2 red[256];

    const int t = threadIdx.x, c = blockIdx.x;
    const int tile = c >> 2, kq = c & 3;
    const int n0 = tile * 64, k0 = kq * 768;
    const int n_l = t & 63, kp = t >> 6;
    const int lrow = t >> 3, lc4 = t & 7;
    const int rA = n0 + lrow, rB = n0 + lrow + 32;
    const int swA = lrow * 32 + ((lc4 ^ (lrow & 7)) << 2);
    const int swB = (lrow + 32) * 32 + ((lc4 ^ (lrow & 7)) << 2);
    const float4 z4 = make_float4(0.f, 0.f, 0.f, 0.f);

    ull acc[8];
#pragma unroll
    for (int j = 0; j < 8; j++) acc[j] = 0ULL;
    float isq = 0.f;

    float4 pA, pB, pX = z4;
    {
        pA = (rA < NPTS) ? *(const float4*)(img + (size_t)rA * DDIM + k0 + lc4 * 4) : z4;
        pB = (rB < NPTS) ? *(const float4*)(img + (size_t)rB * DDIM + k0 + lc4 * 4) : z4;
        if (t < 128) pX = ((const float4*)(g_xt + (size_t)k0 * 16))[t];
        *(float4*)&sbuf[0][swA] = pA;
        *(float4*)&sbuf[0][swB] = pB;
        if (t < 128) ((float4*)xts[0])[t] = pX;
    }
    __syncthreads();

    const int p0 = n_l * 32 + (((2 * kp) ^ (n_l & 7)) << 2);
    const int p1 = n_l * 32 + (((2 * kp + 1) ^ (n_l & 7)) << 2);
    const int xo = kp * 8 * 16;

    for (int ch = 0; ch < 24; ch++) {
        const int s = ch & 1;
        if (ch + 1 < 24) {
            int kk0 = k0 + (ch + 1) * 32;
            pA = (rA < NPTS) ? *(const float4*)(img + (size_t)rA * DDIM + kk0 + lc4 * 4) : z4;
            pB = (rB < NPTS) ? *(const float4*)(img + (size_t)rB * DDIM + kk0 + lc4 * 4) : z4;
            if (t < 128) pX = ((const float4*)(g_xt + (size_t)kk0 * 16))[t];
        }
        const float* sb = sbuf[s];
        const float* xt = xts[s];
        float4 v0 = *(const float4*)&sb[p0];
        float4 v1 = *(const float4*)&sb[p1];
        float fv[8] = { v0.x, v0.y, v0.z, v0.w, v1.x, v1.y, v1.z, v1.w };
#pragma unroll
        for (int kk = 0; kk < 8; kk++) {
            float f = fv[kk];
            isq = fmaf(f, f, isq);
            ull dv = dup2(f);
            const ulonglong2* xr = (const ulonglong2*)(xt + xo + kk * 16);
#pragma unroll
            for (int j = 0; j < 4; j++) {
                ulonglong2 u = xr[j];
                fma2(acc[2 * j],     u.x, dv);
                fma2(acc[2 * j + 1], u.y, dv);
            }
        }
        __syncthreads();
        if (ch + 1 < 24) {
            *(float4*)&sbuf[s ^ 1][swA] = pA;
            *(float4*)&sbuf[s ^ 1][swB] = pB;
            if (t < 128) ((float4*)xts[s ^ 1])[t] = pX;
            __syncthreads();
        }
    }

#pragma unroll 1
    for (int bp = 0; bp < 8; bp++) {
        __syncthreads();
        float lo, hi; unpack2(acc[bp], lo, hi);
        red[t] = make_float2(lo, hi);
        __syncthreads();
        if (t < 64) {
            float2 s0 = red[t], s1 = red[t + 64], s2 = red[t + 128], s3 = red[t + 192];
            float sx = s0.x + s1.x + s2.x + s3.x;
            float sy = s0.y + s1.y + s2.y + s3.y;
            int n = n0 + t;
            if (n < NPTS) {
                g_cp[(kq * 16 + 2 * bp) * NPAD + n] = sx;
                g_cp[(kq * 16 + 2 * bp + 1) * NPAD + n] = sy;
            }
        }
    }
    __syncthreads();
    ((float*)red)[t] = isq;
    __syncthreads();
    if (t < 64) {
        const float* r = (const float*)red;
        float s = r[t] + r[t + 64] + r[t + 128] + r[t + 192];
        int n = n0 + t;
        if (n < NPTS) g_ip[kq * NPAD + n] = s;
    }
}

// ---- L2: sm — fused softmax (128 CTAs, all co-resident, grid barrier) ----
__global__ __launch_bounds__(256) void sm() {
    const int t = threadIdx.x, c = blockIdx.x;
    __shared__ float wm[8];

    // phase A (= old s1): logits + per-(b,seg) max
    {
        const int b = c >> 3, seg = c & 7;
        const float c1 = g_c[2], c2 = g_c[3];
        const int nbase = seg * 1252;
        const int nend = min(nbase + 1252, NPTS);
        float m = -1e30f;
        for (int i = nbase + t; i < nend; i += 256) {
            float cr = g_cp[b * NPAD + i] + g_cp[(16 + b) * NPAD + i]
                     + g_cp[(32 + b) * NPAD + i] + g_cp[(48 + b) * NPAD + i];
            float qq = g_ip[i] + g_ip[NPAD + i] + g_ip[2 * NPAD + i] + g_ip[3 * NPAD + i];
            float lg = fmaf(c1, cr, c2 * qq);
            g_lg[b * NPAD + i] = lg;
            m = fmaxf(m, lg);
        }
        for (int o = 16; o; o >>= 1) m = fmaxf(m, __shfl_xor_sync(0xffffffffu, m, o));
        if ((t & 31) == 0) wm[t >> 5] = m;
        __syncthreads();
        if (t == 0) {
            float v = wm[0];
            for (int w = 1; w < 8; w++) v = fmaxf(v, wm[w]);
            g_pmax[c] = v;
        }
    }
    // grid barrier (128 CTAs <= 148 SMs: all resident)
    __syncthreads();
    if (t == 0) {
        __threadfence();
        atomicAdd(&g_barc, 1u);
        while (atomicAdd(&g_barc, 0u) < 128u) {}
    }
    __syncthreads();
    __threadfence();

    // phase B (= old s3): exp + unnormalized w + partial sums
    {
        const int bb = t & 15, nn = t >> 4;
        const float L2E = 1.44269504088896340736f;
        float M = g_pmax[bb * 8];
#pragma unroll
        for (int s = 1; s < 8; s++) M = fmaxf(M, g_pmax[bb * 8 + s]);
        const int base = c * 79;
        float sum = 0.f;
#pragma unroll
        for (int r = 0; r < 5; r++) {
            int n = base + nn + 16 * r;
            if (n < base + 79 && n < NPTS) {
                float e = exp2f((g_lg[bb * NPAD + n] - M) * L2E);
                g_w[n * 16 + bb] = e;
                sum += e;
            }
        }
        sum += __shfl_xor_sync(0xffffffffu, sum, 16);
        __shared__ float smb[8 * 16];
        if ((t & 31) < 16) smb[(t >> 5) * 16 + bb] = sum;
        __syncthreads();
        if (t < 16) {
            float s = 0.f;
            for (int w = 0; w < 8; w++) s += smb[w * 16 + t];
            g_psum[t * 128 + c] = s;
        }
    }
}

// ---- L3: k3 (capture index 3 — profiled this round) ----
__global__ __launch_bounds__(256) void k3(const float* __restrict__ img) {
    __shared__ float red[256 * 8];
    const int t = threadIdx.x, c = blockIdx.x;
    const int dtile = c >> 2, quarter = c & 3;
    const int dt = t & 7, bh = (t >> 3) & 1, p = t >> 4;
    const int dbase = dtile * 32 + dt * 4;
    const int q0 = quarter * 2500;

    ull acc[4][4];
#pragma unroll
    for (int i = 0; i < 4; i++)
#pragma unroll
        for (int j = 0; j < 4; j++) acc[i][j] = 0ULL;

#pragma unroll 2
    for (int j = 0; j < 156; j += 2) {
        int n1 = q0 + p + 16 * j, n2 = n1 + 16;
        float4 i1 = *(const float4*)(img + (size_t)n1 * DDIM + dbase);
        float4 i2 = *(const float4*)(img + (size_t)n2 * DDIM + dbase);
        ulonglong2 wa1 = *(const ulonglong2*)(g_w + (size_t)n1 * 16 + bh * 8);
        ulonglong2 wb1 = *(const ulonglong2*)(g_w + (size_t)n1 * 16 + bh * 8 + 4);
        ulonglong2 wa2 = *(const ulonglong2*)(g_w + (size_t)n2 * 16 + bh * 8);
        ulonglong2 wb2 = *(const ulonglong2*)(g_w + (size_t)n2 * 16 + bh * 8 + 4);
#pragma unroll
        for (int d = 0; d < 4; d++) {
            ull dv = dup2((&i1.x)[d]);
            fma2(acc[0][d], wa1.x, dv);
            fma2(acc[1][d], wa1.y, dv);
            fma2(acc[2][d], wb1.x, dv);
            fma2(acc[3][d], wb1.y, dv);
        }
#pragma unroll
        for (int d = 0; d < 4; d++) {
            ull dv = dup2((&i2.x)[d]);
            fma2(acc[0][d], wa2.x, dv);
            fma2(acc[1][d], wa2.y, dv);
            fma2(acc[2][d], wb2.x, dv);
            fma2(acc[3][d], wb2.y, dv);
        }
    }
    if (p < 4) {
        int n = q0 + 2496 + p;
        float4 i1 = *(const float4*)(img + (size_t)n * DDIM + dbase);
        ulonglong2 wa = *(const ulonglong2*)(g_w + (size_t)n * 16 + bh * 8);
        ulonglong2 wb = *(const ulonglong2*)(g_w + (size_t)n * 16 + bh * 8 + 4);
#pragma unroll
        for (int d = 0; d < 4; d++) {
            ull dv = dup2((&i1.x)[d]);
            fma2(acc[0][d], wa.x, dv);
            fma2(acc[1][d], wa.y, dv);
            fma2(acc[2][d], wb.x, dv);
            fma2(acc[3][d], wb.y, dv);
        }
    }

#pragma unroll 1
    for (int bp = 0; bp < 4; bp++) {
        __syncthreads();
#pragma unroll
        for (int d = 0; d < 4; d++) {
            float lo, hi; unpack2(acc[bp][d], lo, hi);
            red[t * 8 + 2 * d] = lo;
            red[t * 8 + 2 * d + 1] = hi;
        }
        __syncthreads();
        if (t < 128) {
            int h = t & 1, d = (t >> 1) & 3, dtw = (t >> 3) & 7, bhw = t >> 6;
            float s = 0.f;
#pragma unroll
            for (int p2 = 0; p2 < 16; p2++)
                s += red[(dtw + bhw * 8 + p2 * 16) * 8 + 2 * d + h];
            int b = bhw * 8 + bp * 2 + h;
            g_mp[(quarter * 16 + b) * DDIM + dtile * 32 + dtw * 4 + d] = s;
        }
    }
}

// ---- L4: k4 ----
__global__ __launch_bounds__(256) void k4(const float* __restrict__ x,
                                          float* __restrict__ out) {
    const int t = threadIdx.x, c = blockIdx.x;
    const int blo = (c * 1024) / DDIM;
    const int bhi = ((c + 1) * 1024 - 1) / DDIM;
    __shared__ float wsum[8];
    __shared__ float invs[2];
    {
        int myb = (t < 128) ? blo : bhi;
        float s = g_psum[myb * 128 + (t & 127)];
        for (int o = 16; o; o >>= 1) s += __shfl_xor_sync(0xffffffffu, s, o);
        if ((t & 31) == 0) wsum[t >> 5] = s;
    }
    __syncthreads();
    if (t == 0)   invs[0] = 1.f / (wsum[0] + wsum[1] + wsum[2] + wsum[3]);
    if (t == 128) invs[1] = 1.f / (wsum[4] + wsum[5] + wsum[6] + wsum[7]);
    __syncthreads();

    const float at = g_c[0], bt2 = g_c[1];
    int i = (c * 256 + t) * 4;
    int b = i / DDIM;
    int d = i - b * DDIM;
    float inv = (b == blo) ? invs[0] : invs[1];
    float4 m0 = *(const float4*)(g_mp + (size_t)b * DDIM + d);
    float4 m1 = *(const float4*)(g_mp + (size_t)(16 + b) * DDIM + d);
    float4 m2 = *(const float4*)(g_mp + (size_t)(32 + b) * DDIM + d);
    float4 m3 = *(const float4*)(g_mp + (size_t)(48 + b) * DDIM + d);
    float4 xv = *(const float4*)(x + i);
    float sc = at * inv / bt2;
    float4 o;
    o.x = sc * (m0.x + m1.x + m2.x + m3.x) - xv.x / bt2;
    o.y = sc * (m0.y + m1.y + m2.y + m3.y) - xv.y / bt2;
    o.z = sc * (m0.z + m1.z + m2.z + m3.z) - xv.z / bt2;
    o.w = sc * (m0.w + m1.w + m2.w + m3.w) - xv.w / bt2;
    *(float4*)(out + i) = o;
}

extern "C" void kernel_launch(void* const* d_in, const int* in_sizes, int n_in,
                              void* d_out, int out_size) {
    const float* x    = (const float*)d_in[0];
    const float* img  = (const float*)d_in[1];
    const float* sval = (const float*)d_in[2];
    float* out = (float*)d_out;

    ktrc<<<192, 256>>>(x, sval);   // 0
    k1<<<628, 256>>>(img);         // 1
    sm<<<128, 256>>>();            // 2
    k3<<<384, 256>>>(img);         // 3  <- capture lands here
    k4<<<48, 256>>>(x, out);       // 4
}

// round 10
// speedup vs baseline: 1.3156x; 1.2018x over previous
#include <cuda_runtime.h>
#include <cstdint>

typedef unsigned long long ull;

#define NPTS  10000
#define NPAD  10016
#define DDIM  3072

__device__ __align__(16) float g_cp[4 * 16 * NPAD];
__device__ __align__(16) float g_ip[4 * NPAD];
__device__ __align__(16) float g_lg[16 * NPAD];
__device__ __align__(16) float g_w [NPAD * 16];
__device__ __align__(16) float g_mp[4 * 16 * DDIM];
__device__ __align__(16) float g_xt[DDIM * 16];
__device__ float g_pmax[16 * 8];
__device__ float g_psum[16 * 128];
__device__ float g_c[4];
__device__ unsigned g_barc;

__device__ __forceinline__ ull dup2(float v) {
    ull r; asm("mov.b64 %0, {%1, %1};" : "=l"(r) : "f"(v)); return r;
}
__device__ __forceinline__ void fma2(ull& d, ull a, ull b) {
    asm("fma.rn.f32x2 %0, %1, %2, %0;" : "+l"(d) : "l"(a), "l"(b));
}
__device__ __forceinline__ void unpack2(ull v, float& lo, float& hi) {
    asm("mov.b64 {%0, %1}, %2;" : "=f"(lo), "=f"(hi) : "l"(v));
}

// ---- L0: transpose x + constants + barrier reset ----
__global__ __launch_bounds__(256) void ktrc(const float* __restrict__ x,
                                            const float* __restrict__ sval) {
    int i = blockIdx.x * 256 + threadIdx.x;
    if (i < DDIM * 16) {
        int b = i & 15, k = i >> 4;
        g_xt[i] = x[b * DDIM + k];
    }
    if (i == 0) {
        float s = sval[0];
        float at = sqrtf(1.f - s);
        g_c[0] = at; g_c[1] = s;
        g_c[2] = at / s;
        g_c[3] = -(at * at) / (2.f * s);
        g_barc = 0u;
    }
}

// ---- L1: k1 (R4-proven): 628 CTAs x 256 ----
__global__ __launch_bounds__(256) void k1(const float* __restrict__ img) {
    __shared__ float sbuf[2][64 * 32];
    __shared__ float xts[2][32 * 16];
    __shared__ float2 red[256];

    const int t = threadIdx.x, c = blockIdx.x;
    const int tile = c >> 2, kq = c & 3;
    const int n0 = tile * 64, k0 = kq * 768;
    const int n_l = t & 63, kp = t >> 6;
    const int lrow = t >> 3, lc4 = t & 7;
    const int rA = n0 + lrow, rB = n0 + lrow + 32;
    const int swA = lrow * 32 + ((lc4 ^ (lrow & 7)) << 2);
    const int swB = (lrow + 32) * 32 + ((lc4 ^ (lrow & 7)) << 2);
    const float4 z4 = make_float4(0.f, 0.f, 0.f, 0.f);

    ull acc[8];
#pragma unroll
    for (int j = 0; j < 8; j++) acc[j] = 0ULL;
    float isq = 0.f;

    float4 pA, pB, pX = z4;
    {
        pA = (rA < NPTS) ? *(const float4*)(img + (size_t)rA * DDIM + k0 + lc4 * 4) : z4;
        pB = (rB < NPTS) ? *(const float4*)(img + (size_t)rB * DDIM + k0 + lc4 * 4) : z4;
        if (t < 128) pX = ((const float4*)(g_xt + (size_t)k0 * 16))[t];
        *(float4*)&sbuf[0][swA] = pA;
        *(float4*)&sbuf[0][swB] = pB;
        if (t < 128) ((float4*)xts[0])[t] = pX;
    }
    __syncthreads();

    const int p0 = n_l * 32 + (((2 * kp) ^ (n_l & 7)) << 2);
    const int p1 = n_l * 32 + (((2 * kp + 1) ^ (n_l & 7)) << 2);
    const int xo = kp * 8 * 16;

    for (int ch = 0; ch < 24; ch++) {
        const int s = ch & 1;
        if (ch + 1 < 24) {
            int kk0 = k0 + (ch + 1) * 32;
            pA = (rA < NPTS) ? *(const float4*)(img + (size_t)rA * DDIM + kk0 + lc4 * 4) : z4;
            pB = (rB < NPTS) ? *(const float4*)(img + (size_t)rB * DDIM + kk0 + lc4 * 4) : z4;
            if (t < 128) pX = ((const float4*)(g_xt + (size_t)kk0 * 16))[t];
        }
        const float* sb = sbuf[s];
        const float* xt = xts[s];
        float4 v0 = *(const float4*)&sb[p0];
        float4 v1 = *(const float4*)&sb[p1];
        float fv[8] = { v0.x, v0.y, v0.z, v0.w, v1.x, v1.y, v1.z, v1.w };
#pragma unroll
        for (int kk = 0; kk < 8; kk++) {
            float f = fv[kk];
            isq = fmaf(f, f, isq);
            ull dv = dup2(f);
            const ulonglong2* xr = (const ulonglong2*)(xt + xo + kk * 16);
#pragma unroll
            for (int j = 0; j < 4; j++) {
                ulonglong2 u = xr[j];
                fma2(acc[2 * j],     u.x, dv);
                fma2(acc[2 * j + 1], u.y, dv);
            }
        }
        __syncthreads();
        if (ch + 1 < 24) {
            *(float4*)&sbuf[s ^ 1][swA] = pA;
            *(float4*)&sbuf[s ^ 1][swB] = pB;
            if (t < 128) ((float4*)xts[s ^ 1])[t] = pX;
            __syncthreads();
        }
    }

#pragma unroll 1
    for (int bp = 0; bp < 8; bp++) {
        __syncthreads();
        float lo, hi; unpack2(acc[bp], lo, hi);
        red[t] = make_float2(lo, hi);
        __syncthreads();
        if (t < 64) {
            float2 s0 = red[t], s1 = red[t + 64], s2 = red[t + 128], s3 = red[t + 192];
            float sx = s0.x + s1.x + s2.x + s3.x;
            float sy = s0.y + s1.y + s2.y + s3.y;
            int n = n0 + t;
            if (n < NPTS) {
                g_cp[(kq * 16 + 2 * bp) * NPAD + n] = sx;
                g_cp[(kq * 16 + 2 * bp + 1) * NPAD + n] = sy;
            }
        }
    }
    __syncthreads();
    ((float*)red)[t] = isq;
    __syncthreads();
    if (t < 64) {
        const float* r = (const float*)red;
        float s = r[t] + r[t + 64] + r[t + 128] + r[t + 192];
        int n = n0 + t;
        if (n < NPTS) g_ip[kq * NPAD + n] = s;
    }
}

// ---- L2: sm — fused softmax (128 CTAs, grid barrier) ----
__global__ __launch_bounds__(256) void sm() {
    const int t = threadIdx.x, c = blockIdx.x;
    __shared__ float wm[8];
    {
        const int b = c >> 3, seg = c & 7;
        const float c1 = g_c[2], c2 = g_c[3];
        const int nbase = seg * 1252;
        const int nend = min(nbase + 1252, NPTS);
        float m = -1e30f;
        for (int i = nbase + t; i < nend; i += 256) {
            float cr = g_cp[b * NPAD + i] + g_cp[(16 + b) * NPAD + i]
                     + g_cp[(32 + b) * NPAD + i] + g_cp[(48 + b) * NPAD + i];
            float qq = g_ip[i] + g_ip[NPAD + i] + g_ip[2 * NPAD + i] + g_ip[3 * NPAD + i];
            float lg = fmaf(c1, cr, c2 * qq);
            g_lg[b * NPAD + i] = lg;
            m = fmaxf(m, lg);
        }
        for (int o = 16; o; o >>= 1) m = fmaxf(m, __shfl_xor_sync(0xffffffffu, m, o));
        if ((t & 31) == 0) wm[t >> 5] = m;
        __syncthreads();
        if (t == 0) {
            float v = wm[0];
            for (int w = 1; w < 8; w++) v = fmaxf(v, wm[w]);
            g_pmax[c] = v;
        }
    }
    __syncthreads();
    if (t == 0) {
        __threadfence();
        atomicAdd(&g_barc, 1u);
        while (atomicAdd(&g_barc, 0u) < 128u) {}
    }
    __syncthreads();
    __threadfence();
    {
        const int bb = t & 15, nn = t >> 4;
        const float L2E = 1.44269504088896340736f;
        float M = g_pmax[bb * 8];
#pragma unroll
        for (int s = 1; s < 8; s++) M = fmaxf(M, g_pmax[bb * 8 + s]);
        const int base = c * 79;
        float sum = 0.f;
#pragma unroll
        for (int r = 0; r < 5; r++) {
            int n = base + nn + 16 * r;
            if (n < base + 79 && n < NPTS) {
                float e = exp2f((g_lg[bb * NPAD + n] - M) * L2E);
                g_w[n * 16 + bb] = e;
                sum += e;
            }
        }
        sum += __shfl_xor_sync(0xffffffffu, sum, 16);
        __shared__ float smb[8 * 16];
        if ((t & 31) < 16) smb[(t >> 5) * 16 + bb] = sum;
        __syncthreads();
        if (t < 16) {
            float s = 0.f;
            for (int w = 0; w < 8; w++) s += smb[w * 16 + t];
            g_psum[t * 128 + c] = s;
        }
    }
}

// ---- L3: k3 with img prefetched one body ahead (capture index 3) ----
__global__ __launch_bounds__(256, 3) void k3(const float* __restrict__ img) {
    __shared__ float red[256 * 8];
    const int t = threadIdx.x, c = blockIdx.x;
    const int dtile = c >> 2, quarter = c & 3;
    const int dt = t & 7, bh = (t >> 3) & 1, p = t >> 4;
    const int dbase = dtile * 32 + dt * 4;
    const int q0 = quarter * 2500;
    const float* ib = img + (size_t)(q0 + p) * DDIM + dbase;
    const float* wb = g_w + (size_t)(q0 + p) * 16 + bh * 8;

    ull acc[4][4];
#pragma unroll
    for (int i = 0; i < 4; i++)
#pragma unroll
        for (int j = 0; j < 4; j++) acc[i][j] = 0ULL;

    // bodies m=0..77: rows rel 32m and 32m+16. img prefetch 1 body ahead.
    float4 iA1 = *(const float4*)(ib);
    float4 iA2 = *(const float4*)(ib + (size_t)16 * DDIM);
#pragma unroll 1
    for (int m = 0; m < 78; m++) {
        const int mn = (m + 1 < 78) ? m + 1 : 77;    // clamped prefetch (no OOB)
        float4 iB1 = *(const float4*)(ib + (size_t)(32 * mn) * DDIM);
        float4 iB2 = *(const float4*)(ib + (size_t)(32 * mn + 16) * DDIM);
        ulonglong2 wa1 = *(const ulonglong2*)(wb + (size_t)(32 * m) * 16);
        ulonglong2 wb1 = *(const ulonglong2*)(wb + (size_t)(32 * m) * 16 + 4);
        ulonglong2 wa2 = *(const ulonglong2*)(wb + (size_t)(32 * m + 16) * 16);
        ulonglong2 wb2 = *(const ulonglong2*)(wb + (size_t)(32 * m + 16) * 16 + 4);
#pragma unroll
        for (int d = 0; d < 4; d++) {
            ull dv = dup2((&iA1.x)[d]);
            fma2(acc[0][d], wa1.x, dv);
            fma2(acc[1][d], wa1.y, dv);
            fma2(acc[2][d], wb1.x, dv);
            fma2(acc[3][d], wb1.y, dv);
        }
#pragma unroll
        for (int d = 0; d < 4; d++) {
            ull dv = dup2((&iA2.x)[d]);
            fma2(acc[0][d], wa2.x, dv);
            fma2(acc[1][d], wa2.y, dv);
            fma2(acc[2][d], wb2.x, dv);
            fma2(acc[3][d], wb2.y, dv);
        }
        iA1 = iB1; iA2 = iB2;
    }
    if (p < 4) {   // tail rows rel 2496..2499
        int n = q0 + 2496 + p;
        float4 i1 = *(const float4*)(img + (size_t)n * DDIM + dbase);
        ulonglong2 wa = *(const ulonglong2*)(g_w + (size_t)n * 16 + bh * 8);
        ulonglong2 wbt = *(const ulonglong2*)(g_w + (size_t)n * 16 + bh * 8 + 4);
#pragma unroll
        for (int d = 0; d < 4; d++) {
            ull dv = dup2((&i1.x)[d]);
            fma2(acc[0][d], wa.x, dv);
            fma2(acc[1][d], wa.y, dv);
            fma2(acc[2][d], wbt.x, dv);
            fma2(acc[3][d], wbt.y, dv);
        }
    }

#pragma unroll 1
    for (int bp = 0; bp < 4; bp++) {
        __syncthreads();
#pragma unroll
        for (int d = 0; d < 4; d++) {
            float lo, hi; unpack2(acc[bp][d], lo, hi);
            red[t * 8 + 2 * d] = lo;
            red[t * 8 + 2 * d + 1] = hi;
        }
        __syncthreads();
        if (t < 128) {
            int h = t & 1, d = (t >> 1) & 3, dtw = (t >> 3) & 7, bhw = t >> 6;
            float s = 0.f;
#pragma unroll
            for (int p2 = 0; p2 < 16; p2++)
                s += red[(dtw + bhw * 8 + p2 * 16) * 8 + 2 * d + h];
            int b = bhw * 8 + bp * 2 + h;
            g_mp[(quarter * 16 + b) * DDIM + dtile * 32 + dtw * 4 + d] = s;
        }
    }
}

// ---- L4: k4 ----
__global__ __launch_bounds__(256) void k4(const float* __restrict__ x,
                                          float* __restrict__ out) {
    const int t = threadIdx.x, c = blockIdx.x;
    const int blo = (c * 1024) / DDIM;
    const int bhi = ((c + 1) * 1024 - 1) / DDIM;
    __shared__ float wsum[8];
    __shared__ float invs[2];
    {
        int myb = (t < 128) ? blo : bhi;
        float s = g_psum[myb * 128 + (t & 127)];
        for (int o = 16; o; o >>= 1) s += __shfl_xor_sync(0xffffffffu, s, o);
        if ((t & 31) == 0) wsum[t >> 5] = s;
    }
    __syncthreads();
    if (t == 0)   invs[0] = 1.f / (wsum[0] + wsum[1] + wsum[2] + wsum[3]);
    if (t == 128) invs[1] = 1.f / (wsum[4] + wsum[5] + wsum[6] + wsum[7]);
    __syncthreads();

    const float at = g_c[0], bt2 = g_c[1];
    int i = (c * 256 + t) * 4;
    int b = i / DDIM;
    int d = i - b * DDIM;
    float inv = (b == blo) ? invs[0] : invs[1];
    float4 m0 = *(const float4*)(g_mp + (size_t)b * DDIM + d);
    float4 m1 = *(const float4*)(g_mp + (size_t)(16 + b) * DDIM + d);
    float4 m2 = *(const float4*)(g_mp + (size_t)(32 + b) * DDIM + d);
    float4 m3 = *(const float4*)(g_mp + (size_t)(48 + b) * DDIM + d);
    float4 xv = *(const float4*)(x + i);
    float sc = at * inv / bt2;
    float4 o;
    o.x = sc * (m0.x + m1.x + m2.x + m3.x) - xv.x / bt2;
    o.y = sc * (m0.y + m1.y + m2.y + m3.y) - xv.y / bt2;
    o.z = sc * (m0.z + m1.z + m2.z + m3.z) - xv.z / bt2;
    o.w = sc * (m0.w + m1.w + m2.w + m3.w) - xv.w / bt2;
    *(float4*)(out + i) = o;
}

extern "C" void kernel_launch(void* const* d_in, const int* in_sizes, int n_in,
                              void* d_out, int out_size) {
    const float* x    = (const float*)d_in[0];
    const float* img  = (const float*)d_in[1];
    const float* sval = (const float*)d_in[2];
    float* out = (float*)d_out;

    ktrc<<<192, 256>>>(x, sval);   // 0
    k1<<<628, 256>>>(img);         // 1
    sm<<<128, 256>>>();            // 2
    k3<<<384, 256>>>(img);         // 3  <- capture lands here
    k4<<<48, 256>>>(x, out);       // 4
}

// round 11
// speedup vs baseline: 1.6222x; 1.2331x over previous
#include <cuda_runtime.h>
#include <cstdint>

typedef unsigned long long ull;

#define NPTS  10000
#define NPAD  10016
#define DDIM  3072

__device__ __align__(16) float g_cp[4 * 16 * NPAD];
__device__ __align__(16) float g_ip[4 * NPAD];
__device__ __align__(16) float g_lg[16 * NPAD];
__device__ __align__(16) float g_w [NPAD * 16];
__device__ __align__(16) float g_mp[4 * 16 * DDIM];
__device__ __align__(16) float g_xt[DDIM * 16];
__device__ float g_pmax[16 * 8];
__device__ float g_psum[16 * 128];
__device__ float g_c[4];
__device__ unsigned g_barc;

__device__ __forceinline__ ull dup2(float v) {
    ull r; asm("mov.b64 %0, {%1, %1};" : "=l"(r) : "f"(v)); return r;
}
__device__ __forceinline__ void fma2(ull& d, ull a, ull b) {
    asm("fma.rn.f32x2 %0, %1, %2, %0;" : "+l"(d) : "l"(a), "l"(b));
}
__device__ __forceinline__ void unpack2(ull v, float& lo, float& hi) {
    asm("mov.b64 {%0, %1}, %2;" : "=f"(lo), "=f"(hi) : "l"(v));
}
__device__ __forceinline__ void cpa16(uint32_t d, const float* s) {
    asm volatile("cp.async.ca.shared.global [%0], [%1], 16;" :: "r"(d), "l"(s));
}
#define CPCOMMIT() asm volatile("cp.async.commit_group;")
#define CPWAIT(n)  asm volatile("cp.async.wait_group %0;" :: "n"(n) : "memory")

// ---- L0: transpose x + constants + barrier reset ----
__global__ __launch_bounds__(256) void ktrc(const float* __restrict__ x,
                                            const float* __restrict__ sval) {
    int i = blockIdx.x * 256 + threadIdx.x;
    if (i < DDIM * 16) {
        int b = i & 15, k = i >> 4;
        g_xt[i] = x[b * DDIM + k];
    }
    if (i == 0) {
        float s = sval[0];
        float at = sqrtf(1.f - s);
        g_c[0] = at; g_c[1] = s;
        g_c[2] = at / s;
        g_c[3] = -(at * at) / (2.f * s);
        g_barc = 0u;
    }
}

// ---- L1: k1 (R4-proven): 628 CTAs x 256 ----
__global__ __launch_bounds__(256) void k1(const float* __restrict__ img) {
    __shared__ float sbuf[2][64 * 32];
    __shared__ float xts[2][32 * 16];
    __shared__ float2 red[256];

    const int t = threadIdx.x, c = blockIdx.x;
    const int tile = c >> 2, kq = c & 3;
    const int n0 = tile * 64, k0 = kq * 768;
    const int n_l = t & 63, kp = t >> 6;
    const int lrow = t >> 3, lc4 = t & 7;
    const int rA = n0 + lrow, rB = n0 + lrow + 32;
    const int swA = lrow * 32 + ((lc4 ^ (lrow & 7)) << 2);
    const int swB = (lrow + 32) * 32 + ((lc4 ^ (lrow & 7)) << 2);
    const float4 z4 = make_float4(0.f, 0.f, 0.f, 0.f);

    ull acc[8];
#pragma unroll
    for (int j = 0; j < 8; j++) acc[j] = 0ULL;
    float isq = 0.f;

    float4 pA, pB, pX = z4;
    {
        pA = (rA < NPTS) ? *(const float4*)(img + (size_t)rA * DDIM + k0 + lc4 * 4) : z4;
        pB = (rB < NPTS) ? *(const float4*)(img + (size_t)rB * DDIM + k0 + lc4 * 4) : z4;
        if (t < 128) pX = ((const float4*)(g_xt + (size_t)k0 * 16))[t];
        *(float4*)&sbuf[0][swA] = pA;
        *(float4*)&sbuf[0][swB] = pB;
        if (t < 128) ((float4*)xts[0])[t] = pX;
    }
    __syncthreads();

    const int p0 = n_l * 32 + (((2 * kp) ^ (n_l & 7)) << 2);
    const int p1 = n_l * 32 + (((2 * kp + 1) ^ (n_l & 7)) << 2);
    const int xo = kp * 8 * 16;

    for (int ch = 0; ch < 24; ch++) {
        const int s = ch & 1;
        if (ch + 1 < 24) {
            int kk0 = k0 + (ch + 1) * 32;
            pA = (rA < NPTS) ? *(const float4*)(img + (size_t)rA * DDIM + kk0 + lc4 * 4) : z4;
            pB = (rB < NPTS) ? *(const float4*)(img + (size_t)rB * DDIM + kk0 + lc4 * 4) : z4;
            if (t < 128) pX = ((const float4*)(g_xt + (size_t)kk0 * 16))[t];
        }
        const float* sb = sbuf[s];
        const float* xt = xts[s];
        float4 v0 = *(const float4*)&sb[p0];
        float4 v1 = *(const float4*)&sb[p1];
        float fv[8] = { v0.x, v0.y, v0.z, v0.w, v1.x, v1.y, v1.z, v1.w };
#pragma unroll
        for (int kk = 0; kk < 8; kk++) {
            float f = fv[kk];
            isq = fmaf(f, f, isq);
            ull dv = dup2(f);
            const ulonglong2* xr = (const ulonglong2*)(xt + xo + kk * 16);
#pragma unroll
            for (int j = 0; j < 4; j++) {
                ulonglong2 u = xr[j];
                fma2(acc[2 * j],     u.x, dv);
                fma2(acc[2 * j + 1], u.y, dv);
            }
        }
        __syncthreads();
        if (ch + 1 < 24) {
            *(float4*)&sbuf[s ^ 1][swA] = pA;
            *(float4*)&sbuf[s ^ 1][swB] = pB;
            if (t < 128) ((float4*)xts[s ^ 1])[t] = pX;
            __syncthreads();
        }
    }

#pragma unroll 1
    for (int bp = 0; bp < 8; bp++) {
        __syncthreads();
        float lo, hi; unpack2(acc[bp], lo, hi);
        red[t] = make_float2(lo, hi);
        __syncthreads();
        if (t < 64) {
            float2 s0 = red[t], s1 = red[t + 64], s2 = red[t + 128], s3 = red[t + 192];
            float sx = s0.x + s1.x + s2.x + s3.x;
            float sy = s0.y + s1.y + s2.y + s3.y;
            int n = n0 + t;
            if (n < NPTS) {
                g_cp[(kq * 16 + 2 * bp) * NPAD + n] = sx;
                g_cp[(kq * 16 + 2 * bp + 1) * NPAD + n] = sy;
            }
        }
    }
    __syncthreads();
    ((float*)red)[t] = isq;
    __syncthreads();
    if (t < 64) {
        const float* r = (const float*)red;
        float s = r[t] + r[t + 64] + r[t + 128] + r[t + 192];
        int n = n0 + t;
        if (n < NPTS) g_ip[kq * NPAD + n] = s;
    }
}

// ---- L2: sm — fused softmax (128 CTAs, grid barrier) ----
__global__ __launch_bounds__(256) void sm() {
    const int t = threadIdx.x, c = blockIdx.x;
    __shared__ float wm[8];
    {
        const int b = c >> 3, seg = c & 7;
        const float c1 = g_c[2], c2 = g_c[3];
        const int nbase = seg * 1252;
        const int nend = min(nbase + 1252, NPTS);
        float m = -1e30f;
        for (int i = nbase + t; i < nend; i += 256) {
            float cr = g_cp[b * NPAD + i] + g_cp[(16 + b) * NPAD + i]
                     + g_cp[(32 + b) * NPAD + i] + g_cp[(48 + b) * NPAD + i];
            float qq = g_ip[i] + g_ip[NPAD + i] + g_ip[2 * NPAD + i] + g_ip[3 * NPAD + i];
            float lg = fmaf(c1, cr, c2 * qq);
            g_lg[b * NPAD + i] = lg;
            m = fmaxf(m, lg);
        }
        for (int o = 16; o; o >>= 1) m = fmaxf(m, __shfl_xor_sync(0xffffffffu, m, o));
        if ((t & 31) == 0) wm[t >> 5] = m;
        __syncthreads();
        if (t == 0) {
            float v = wm[0];
            for (int w = 1; w < 8; w++) v = fmaxf(v, wm[w]);
            g_pmax[c] = v;
        }
    }
    __syncthreads();
    if (t == 0) {
        __threadfence();
        atomicAdd(&g_barc, 1u);
        while (atomicAdd(&g_barc, 0u) < 128u) {}
    }
    __syncthreads();
    __threadfence();
    {
        const int bb = t & 15, nn = t >> 4;
        const float L2E = 1.44269504088896340736f;
        float M = g_pmax[bb * 8];
#pragma unroll
        for (int s = 1; s < 8; s++) M = fmaxf(M, g_pmax[bb * 8 + s]);
        const int base = c * 79;
        float sum = 0.f;
#pragma unroll
        for (int r = 0; r < 5; r++) {
            int n = base + nn + 16 * r;
            if (n < base + 79 && n < NPTS) {
                float e = exp2f((g_lg[bb * NPAD + n] - M) * L2E);
                g_w[n * 16 + bb] = e;
                sum += e;
            }
        }
        sum += __shfl_xor_sync(0xffffffffu, sum, 16);
        __shared__ float smb[8 * 16];
        if ((t & 31) < 16) smb[(t >> 5) * 16 + bb] = sum;
        __syncthreads();
        if (t < 16) {
            float s = 0.f;
            for (int w = 0; w < 8; w++) s += smb[w * 16 + t];
            g_psum[t * 128 + c] = s;
        }
    }
}

// ---- L3: k3 with cp.async img+w rings, depth 4 (capture index 3) ----
__global__ __launch_bounds__(256, 3) void k3(const float* __restrict__ img) {
    __shared__ float si[4][1024];    // img ring: 32 n x 32 d per body
    __shared__ float sw[4][512];     // w ring:   32 n x 16 b per body
    __shared__ float red[256 * 8];
    const int t = threadIdx.x, c = blockIdx.x;
    const int dtile = c >> 2, quarter = c & 3;
    const int dt = t & 7, bh = (t >> 3) & 1, p = t >> 4;
    const int q0 = quarter * 2500;
    const uint32_t ui = (uint32_t)__cvta_generic_to_shared(si);
    const uint32_t uw = (uint32_t)__cvta_generic_to_shared(sw);
    const uint32_t di = (uint32_t)(((t >> 3) * 32 + (t & 7) * 4) * 4);
    const float* isrc = img + (size_t)(q0 + (t >> 3)) * DDIM + dtile * 32 + (t & 7) * 4;
    const float* wsrc = g_w + (size_t)q0 * 16 + t * 4;

    ull acc[4][4];
#pragma unroll
    for (int i = 0; i < 4; i++)
#pragma unroll
        for (int j = 0; j < 4; j++) acc[i][j] = 0ULL;

    // prologue: stage bodies 0..2
#pragma unroll
    for (int m = 0; m < 3; m++) {
        cpa16(ui + (uint32_t)(m * 4096) + di, isrc + (size_t)(32 * m) * DDIM);
        if (t < 128) cpa16(uw + (uint32_t)(m * 2048 + t * 16), wsrc + 32 * m * 16);
        CPCOMMIT();
    }

#pragma unroll 1
    for (int m = 0; m < 78; m++) {
        CPWAIT(2);
        __syncthreads();
        if (m + 3 < 78) {
            const int m3 = m + 3;
            cpa16(ui + (uint32_t)((m3 & 3) * 4096) + di, isrc + (size_t)(32 * m3) * DDIM);
            if (t < 128) cpa16(uw + (uint32_t)((m3 & 3) * 2048 + t * 16), wsrc + (size_t)(32 * m3) * 16);
        }
        CPCOMMIT();
        const float* sif = si[m & 3];
        const float* swf = sw[m & 3];
        float4 i1 = *(const float4*)&sif[p * 32 + dt * 4];
        float4 i2 = *(const float4*)&sif[(p + 16) * 32 + dt * 4];
        ulonglong2 wa1 = *(const ulonglong2*)&swf[p * 16 + bh * 8];
        ulonglong2 wb1 = *(const ulonglong2*)&swf[p * 16 + bh * 8 + 4];
        ulonglong2 wa2 = *(const ulonglong2*)&swf[(p + 16) * 16 + bh * 8];
        ulonglong2 wb2 = *(const ulonglong2*)&swf[(p + 16) * 16 + bh * 8 + 4];
#pragma unroll
        for (int d = 0; d < 4; d++) {
            ull dv = dup2((&i1.x)[d]);
            fma2(acc[0][d], wa1.x, dv);
            fma2(acc[1][d], wa1.y, dv);
            fma2(acc[2][d], wb1.x, dv);
            fma2(acc[3][d], wb1.y, dv);
        }
#pragma unroll
        for (int d = 0; d < 4; d++) {
            ull dv = dup2((&i2.x)[d]);
            fma2(acc[0][d], wa2.x, dv);
            fma2(acc[1][d], wa2.y, dv);
            fma2(acc[2][d], wb2.x, dv);
            fma2(acc[3][d], wb2.y, dv);
        }
    }
    // tail rows rel 2496..2499
    if (p < 4) {
        int n = q0 + 2496 + p;
        const int dbase = dtile * 32 + dt * 4;
        float4 i1 = *(const float4*)(img + (size_t)n * DDIM + dbase);
        ulonglong2 wa = *(const ulonglong2*)(g_w + (size_t)n * 16 + bh * 8);
        ulonglong2 wbt = *(const ulonglong2*)(g_w + (size_t)n * 16 + bh * 8 + 4);
#pragma unroll
        for (int d = 0; d < 4; d++) {
            ull dv = dup2((&i1.x)[d]);
            fma2(acc[0][d], wa.x, dv);
            fma2(acc[1][d], wa.y, dv);
            fma2(acc[2][d], wbt.x, dv);
            fma2(acc[3][d], wbt.y, dv);
        }
    }

#pragma unroll 1
    for (int bp = 0; bp < 4; bp++) {
        __syncthreads();
#pragma unroll
        for (int d = 0; d < 4; d++) {
            float lo, hi; unpack2(acc[bp][d], lo, hi);
            red[t * 8 + 2 * d] = lo;
            red[t * 8 + 2 * d + 1] = hi;
        }
        __syncthreads();
        if (t < 128) {
            int h = t & 1, d = (t >> 1) & 3, dtw = (t >> 3) & 7, bhw = t >> 6;
            float s = 0.f;
#pragma unroll
            for (int p2 = 0; p2 < 16; p2++)
                s += red[(dtw + bhw * 8 + p2 * 16) * 8 + 2 * d + h];
            int b = bhw * 8 + bp * 2 + h;
            g_mp[(quarter * 16 + b) * DDIM + dtile * 32 + dtw * 4 + d] = s;
        }
    }
}

// ---- L4: k4 ----
__global__ __launch_bounds__(256) void k4(const float* __restrict__ x,
                                          float* __restrict__ out) {
    const int t = threadIdx.x, c = blockIdx.x;
    const int blo = (c * 1024) / DDIM;
    const int bhi = ((c + 1) * 1024 - 1) / DDIM;
    __shared__ float wsum[8];
    __shared__ float invs[2];
    {
        int myb = (t < 128) ? blo : bhi;
        float s = g_psum[myb * 128 + (t & 127)];
        for (int o = 16; o; o >>= 1) s += __shfl_xor_sync(0xffffffffu, s, o);
        if ((t & 31) == 0) wsum[t >> 5] = s;
    }
    __syncthreads();
    if (t == 0)   invs[0] = 1.f / (wsum[0] + wsum[1] + wsum[2] + wsum[3]);
    if (t == 128) invs[1] = 1.f / (wsum[4] + wsum[5] + wsum[6] + wsum[7]);
    __syncthreads();

    const float at = g_c[0], bt2 = g_c[1];
    int i = (c * 256 + t) * 4;
    int b = i / DDIM;
    int d = i - b * DDIM;
    float inv = (b == blo) ? invs[0] : invs[1];
    float4 m0 = *(const float4*)(g_mp + (size_t)b * DDIM + d);
    float4 m1 = *(const float4*)(g_mp + (size_t)(16 + b) * DDIM + d);
    float4 m2 = *(const float4*)(g_mp + (size_t)(32 + b) * DDIM + d);
    float4 m3 = *(const float4*)(g_mp + (size_t)(48 + b) * DDIM + d);
    float4 xv = *(const float4*)(x + i);
    float sc = at * inv / bt2;
    float4 o;
    o.x = sc * (m0.x + m1.x + m2.x + m3.x) - xv.x / bt2;
    o.y = sc * (m0.y + m1.y + m2.y + m3.y) - xv.y / bt2;
    o.z = sc * (m0.z + m1.z + m2.z + m3.z) - xv.z / bt2;
    o.w = sc * (m0.w + m1.w + m2.w + m3.w) - xv.w / bt2;
    *(float4*)(out + i) = o;
}

extern "C" void kernel_launch(void* const* d_in, const int* in_sizes, int n_in,
                              void* d_out, int out_size) {
    const float* x    = (const float*)d_in[0];
    const float* img  = (const float*)d_in[1];
    const float* sval = (const float*)d_in[2];
    float* out = (float*)d_out;

    ktrc<<<192, 256>>>(x, sval);   // 0
    k1<<<628, 256>>>(img);         // 1
    sm<<<128, 256>>>();            // 2
    k3<<<384, 256>>>(img);         // 3  <- capture lands here
    k4<<<48, 256>>>(x, out);       // 4
}

// round 12
// speedup vs baseline: 1.6767x; 1.0336x over previous
#include <cuda_runtime.h>
#include <cstdint>

typedef unsigned long long ull;

#define NPTS  10000
#define NPAD  10016
#define DDIM  3072

__device__ __align__(16) float g_cp[4 * 16 * NPAD];
__device__ __align__(16) float g_ip[4 * NPAD];
__device__ __align__(16) float g_lg[16 * NPAD];
__device__ __align__(16) float g_w [NPAD * 16];
__device__ __align__(16) float g_mp[4 * 16 * DDIM];
__device__ __align__(16) float g_xt[DDIM * 16];
__device__ float g_pmax[16 * 8];
__device__ float g_psum[16 * 128];
__device__ float g_c[4];
__device__ unsigned g_barc;

__device__ __forceinline__ ull dup2(float v) {
    ull r; asm("mov.b64 %0, {%1, %1};" : "=l"(r) : "f"(v)); return r;
}
__device__ __forceinline__ void fma2(ull& d, ull a, ull b) {
    asm("fma.rn.f32x2 %0, %1, %2, %0;" : "+l"(d) : "l"(a), "l"(b));
}
__device__ __forceinline__ void unpack2(ull v, float& lo, float& hi) {
    asm("mov.b64 {%0, %1}, %2;" : "=f"(lo), "=f"(hi) : "l"(v));
}
__device__ __forceinline__ void cpa16(uint32_t d, const float* s) {
    asm volatile("cp.async.ca.shared.global [%0], [%1], 16;" :: "r"(d), "l"(s));
}
__device__ __forceinline__ void cpa16z(uint32_t d, const float* s, int sz) {
    asm volatile("cp.async.ca.shared.global [%0], [%1], 16, %2;" :: "r"(d), "l"(s), "r"(sz));
}
#define CPCOMMIT() asm volatile("cp.async.commit_group;")
#define CPWAIT(n)  asm volatile("cp.async.wait_group %0;" :: "n"(n) : "memory")

// ---- L0a: constants + barrier reset ----
__global__ void kconst(const float* __restrict__ sval) {
    if (threadIdx.x == 0) {
        float s = sval[0];
        float at = sqrtf(1.f - s);
        g_c[0] = at; g_c[1] = s;
        g_c[2] = at / s;
        g_c[3] = -(at * at) / (2.f * s);
        g_barc = 0u;
    }
}
// ---- L0b/L0c: transpose x ----
__global__ __launch_bounds__(256) void ktr(const float* __restrict__ x, int off) {
    int i = off + blockIdx.x * 256 + threadIdx.x;
    if (i < DDIM * 16) {
        int b = i & 15, k = i >> 4;
        g_xt[i] = x[b * DDIM + k];
    }
}

// ---- L3: k1 v2 — 316 CTAs x 256. tile=c>>2 (128 n), kq=c&3 (768 k), 24 chunks of 32 k.
// Thread (n_g=t&31, kp=t>>5): rows n_g+32r (r<4), k=kp*4..+3 per chunk → 128 fma2 : 20 LDS.
__global__ __launch_bounds__(256, 2) void k1(const float* __restrict__ img) {
    __shared__ float si[2][128 * 32];   // img ring, XOR-swizzled float4 columns
    __shared__ float xs[2][32 * 16];    // x ring [k][b]
    __shared__ float2 red2[1024];

    const int t = threadIdx.x, c = blockIdx.x;
    const int tile = c >> 2, kq = c & 3;
    const int n0 = tile * 128, k0 = kq * 768;
    const int n_g = t & 31, kp = t >> 5;
    const int lr0 = t >> 3, lc4 = t & 7;                 // loader: rows lr0+32j, col4 lc4
    const int swc = ((lc4 ^ (lr0 & 7)) << 2);            // swizzled col (floats)
    const uint32_t usi0 = (uint32_t)__cvta_generic_to_shared(si[0]);
    const uint32_t usi1 = (uint32_t)__cvta_generic_to_shared(si[1]);
    const uint32_t uxs0 = (uint32_t)__cvta_generic_to_shared(xs[0]);
    const uint32_t uxs1 = (uint32_t)__cvta_generic_to_shared(xs[1]);

    int rsz[4]; const float* rsrc[4];
#pragma unroll
    for (int j = 0; j < 4; j++) {
        int row = n0 + lr0 + 32 * j;
        rsz[j] = (row < NPTS) ? 16 : 0;
        rsrc[j] = img + (size_t)min(row, NPTS - 1) * DDIM + k0 + lc4 * 4;
    }

    ull acc[4][8];
#pragma unroll
    for (int r = 0; r < 4; r++)
#pragma unroll
        for (int bp = 0; bp < 8; bp++) acc[r][bp] = 0ULL;
    float isq[4] = {0.f, 0.f, 0.f, 0.f};

    // prologue: stage chunk 0
#pragma unroll
    for (int j = 0; j < 4; j++)
        cpa16z(usi0 + (uint32_t)(((lr0 + 32 * j) * 32 + swc) * 4), rsrc[j], rsz[j]);
    if (t < 128) cpa16z(uxs0 + (uint32_t)(t * 16), g_xt + (size_t)k0 * 16 + t * 4, 16);
    CPCOMMIT();

    const int pcol = ((kp ^ (n_g & 7)) << 2);

    for (int ch = 0; ch < 24; ch++) {
        const int s = ch & 1;
        if (ch + 1 < 24) {                               // prefetch into stage s^1
            const uint32_t ub = s ? usi0 : usi1;
            const uint32_t ux = s ? uxs0 : uxs1;
            const int kb = (ch + 1) * 32;
#pragma unroll
            for (int j = 0; j < 4; j++)
                cpa16z(ub + (uint32_t)(((lr0 + 32 * j) * 32 + swc) * 4), rsrc[j] + kb, rsz[j]);
            if (t < 128) cpa16z(ux + (uint32_t)(t * 16), g_xt + (size_t)(k0 + kb) * 16 + t * 4, 16);
        }
        CPCOMMIT();
        CPWAIT(1);
        __syncthreads();
        const float* sif = si[s];
        const float* xsf = xs[s];
        float4 iv[4];
#pragma unroll
        for (int r = 0; r < 4; r++)
            iv[r] = *(const float4*)&sif[(n_g + 32 * r) * 32 + pcol];
#pragma unroll
        for (int kk = 0; kk < 4; kk++) {
            const ulonglong2* xr = (const ulonglong2*)(xsf + (kp * 4 + kk) * 16);
            ulonglong2 u0 = xr[0], u1 = xr[1], u2 = xr[2], u3 = xr[3];
#pragma unroll
            for (int r = 0; r < 4; r++) {
                float f = (&iv[r].x)[kk];
                isq[r] = fmaf(f, f, isq[r]);
                ull dv = dup2(f);
                fma2(acc[r][0], u0.x, dv); fma2(acc[r][1], u0.y, dv);
                fma2(acc[r][2], u1.x, dv); fma2(acc[r][3], u1.y, dv);
                fma2(acc[r][4], u2.x, dv); fma2(acc[r][5], u2.y, dv);
                fma2(acc[r][6], u3.x, dv); fma2(acc[r][7], u3.y, dv);
            }
        }
        __syncthreads();                                  // free stage s for ch+2
    }

    // epilogue: reduce over kp (8) per (row, b)
#pragma unroll 1
    for (int bp = 0; bp < 8; bp++) {
        __syncthreads();
#pragma unroll
        for (int r = 0; r < 4; r++) {
            float lo, hi; unpack2(acc[r][bp], lo, hi);
            red2[(kp * 32 + n_g) * 4 + r] = make_float2(lo, hi);
        }
        __syncthreads();
        if (t < 128) {
            const int ng2 = t & 31, r2 = t >> 5;
            float sx = 0.f, sy = 0.f;
#pragma unroll
            for (int q = 0; q < 8; q++) {
                float2 v = red2[(q * 32 + ng2) * 4 + r2];
                sx += v.x; sy += v.y;
            }
            int n = n0 + t;
            if (n < NPTS) {
                g_cp[(kq * 16 + 2 * bp) * NPAD + n] = sx;
                g_cp[(kq * 16 + 2 * bp + 1) * NPAD + n] = sy;
            }
        }
    }
    __syncthreads();
    {
        float* rf = (float*)red2;
#pragma unroll
        for (int r = 0; r < 4; r++) rf[(kp * 32 + n_g) * 4 + r] = isq[r];
    }
    __syncthreads();
    if (t < 128) {
        const float* rf = (const float*)red2;
        const int ng2 = t & 31, r2 = t >> 5;
        float s = 0.f;
#pragma unroll
        for (int q = 0; q < 8; q++) s += rf[(q * 32 + ng2) * 4 + r2];
        int n = n0 + t;
        if (n < NPTS) g_ip[kq * NPAD + n] = s;
    }
}

// ---- sm — fused softmax (128 CTAs, grid barrier) ----
__global__ __launch_bounds__(256) void sm() {
    const int t = threadIdx.x, c = blockIdx.x;
    __shared__ float wm[8];
    {
        const int b = c >> 3, seg = c & 7;
        const float c1 = g_c[2], c2 = g_c[3];
        const int nbase = seg * 1252;
        const int nend = min(nbase + 1252, NPTS);
        float m = -1e30f;
        for (int i = nbase + t; i < nend; i += 256) {
            float cr = g_cp[b * NPAD + i] + g_cp[(16 + b) * NPAD + i]
                     + g_cp[(32 + b) * NPAD + i] + g_cp[(48 + b) * NPAD + i];
            float qq = g_ip[i] + g_ip[NPAD + i] + g_ip[2 * NPAD + i] + g_ip[3 * NPAD + i];
            float lg = fmaf(c1, cr, c2 * qq);
            g_lg[b * NPAD + i] = lg;
            m = fmaxf(m, lg);
        }
        for (int o = 16; o; o >>= 1) m = fmaxf(m, __shfl_xor_sync(0xffffffffu, m, o));
        if ((t & 31) == 0) wm[t >> 5] = m;
        __syncthreads();
        if (t == 0) {
            float v = wm[0];
            for (int w = 1; w < 8; w++) v = fmaxf(v, wm[w]);
            g_pmax[c] = v;
        }
    }
    __syncthreads();
    if (t == 0) {
        __threadfence();
        atomicAdd(&g_barc, 1u);
        while (atomicAdd(&g_barc, 0u) < 128u) {}
    }
    __syncthreads();
    __threadfence();
    {
        const int bb = t & 15, nn = t >> 4;
        const float L2E = 1.44269504088896340736f;
        float M = g_pmax[bb * 8];
#pragma unroll
        for (int s = 1; s < 8; s++) M = fmaxf(M, g_pmax[bb * 8 + s]);
        const int base = c * 79;
        float sum = 0.f;
#pragma unroll
        for (int r = 0; r < 5; r++) {
            int n = base + nn + 16 * r;
            if (n < base + 79 && n < NPTS) {
                float e = exp2f((g_lg[bb * NPAD + n] - M) * L2E);
                g_w[n * 16 + bb] = e;
                sum += e;
            }
        }
        sum += __shfl_xor_sync(0xffffffffu, sum, 16);
        __shared__ float smb[8 * 16];
        if ((t & 31) < 16) smb[(t >> 5) * 16 + bb] = sum;
        __syncthreads();
        if (t < 16) {
            float s = 0.f;
            for (int w = 0; w < 8; w++) s += smb[w * 16 + t];
            g_psum[t * 128 + c] = s;
        }
    }
}

// ---- k3 (R11-proven): cp.async img+w rings, depth 4 ----
__global__ __launch_bounds__(256, 3) void k3(const float* __restrict__ img) {
    __shared__ float si[4][1024];
    __shared__ float sw[4][512];
    __shared__ float red[256 * 8];
    const int t = threadIdx.x, c = blockIdx.x;
    const int dtile = c >> 2, quarter = c & 3;
    const int dt = t & 7, bh = (t >> 3) & 1, p = t >> 4;
    const int q0 = quarter * 2500;
    const uint32_t ui = (uint32_t)__cvta_generic_to_shared(si);
    const uint32_t uw = (uint32_t)__cvta_generic_to_shared(sw);
    const uint32_t di = (uint32_t)(((t >> 3) * 32 + (t & 7) * 4) * 4);
    const float* isrc = img + (size_t)(q0 + (t >> 3)) * DDIM + dtile * 32 + (t & 7) * 4;
    const float* wsrc = g_w + (size_t)q0 * 16 + t * 4;

    ull acc[4][4];
#pragma unroll
    for (int i = 0; i < 4; i++)
#pragma unroll
        for (int j = 0; j < 4; j++) acc[i][j] = 0ULL;

#pragma unroll
    for (int m = 0; m < 3; m++) {
        cpa16(ui + (uint32_t)(m * 4096) + di, isrc + (size_t)(32 * m) * DDIM);
        if (t < 128) cpa16(uw + (uint32_t)(m * 2048 + t * 16), wsrc + 32 * m * 16);
        CPCOMMIT();
    }

#pragma unroll 1
    for (int m = 0; m < 78; m++) {
        CPWAIT(2);
        __syncthreads();
        if (m + 3 < 78) {
            const int m3 = m + 3;
            cpa16(ui + (uint32_t)((m3 & 3) * 4096) + di, isrc + (size_t)(32 * m3) * DDIM);
            if (t < 128) cpa16(uw + (uint32_t)((m3 & 3) * 2048 + t * 16), wsrc + (size_t)(32 * m3) * 16);
        }
        CPCOMMIT();
        const float* sif = si[m & 3];
        const float* swf = sw[m & 3];
        float4 i1 = *(const float4*)&sif[p * 32 + dt * 4];
        float4 i2 = *(const float4*)&sif[(p + 16) * 32 + dt * 4];
        ulonglong2 wa1 = *(const ulonglong2*)&swf[p * 16 + bh * 8];
        ulonglong2 wb1 = *(const ulonglong2*)&swf[p * 16 + bh * 8 + 4];
        ulonglong2 wa2 = *(const ulonglong2*)&swf[(p + 16) * 16 + bh * 8];
        ulonglong2 wb2 = *(const ulonglong2*)&swf[(p + 16) * 16 + bh * 8 + 4];
#pragma unroll
        for (int d = 0; d < 4; d++) {
            ull dv = dup2((&i1.x)[d]);
            fma2(acc[0][d], wa1.x, dv);
            fma2(acc[1][d], wa1.y, dv);
            fma2(acc[2][d], wb1.x, dv);
            fma2(acc[3][d], wb1.y, dv);
        }
#pragma unroll
        for (int d = 0; d < 4; d++) {
            ull dv = dup2((&i2.x)[d]);
            fma2(acc[0][d], wa2.x, dv);
            fma2(acc[1][d], wa2.y, dv);
            fma2(acc[2][d], wb2.x, dv);
            fma2(acc[3][d], wb2.y, dv);
        }
    }
    if (p < 4) {
        int n = q0 + 2496 + p;
        const int dbase = dtile * 32 + dt * 4;
        float4 i1 = *(const float4*)(img + (size_t)n * DDIM + dbase);
        ulonglong2 wa = *(const ulonglong2*)(g_w + (size_t)n * 16 + bh * 8);
        ulonglong2 wbt = *(const ulonglong2*)(g_w + (size_t)n * 16 + bh * 8 + 4);
#pragma unroll
        for (int d = 0; d < 4; d++) {
            ull dv = dup2((&i1.x)[d]);
            fma2(acc[0][d], wa.x, dv);
            fma2(acc[1][d], wa.y, dv);
            fma2(acc[2][d], wbt.x, dv);
            fma2(acc[3][d], wbt.y, dv);
        }
    }

#pragma unroll 1
    for (int bp = 0; bp < 4; bp++) {
        __syncthreads();
#pragma unroll
        for (int d = 0; d < 4; d++) {
            float lo, hi; unpack2(acc[bp][d], lo, hi);
            red[t * 8 + 2 * d] = lo;
            red[t * 8 + 2 * d + 1] = hi;
        }
        __syncthreads();
        if (t < 128) {
            int h = t & 1, d = (t >> 1) & 3, dtw = (t >> 3) & 7, bhw = t >> 6;
            float s = 0.f;
#pragma unroll
            for (int p2 = 0; p2 < 16; p2++)
                s += red[(dtw + bhw * 8 + p2 * 16) * 8 + 2 * d + h];
            int b = bhw * 8 + bp * 2 + h;
            g_mp[(quarter * 16 + b) * DDIM + dtile * 32 + dtw * 4 + d] = s;
        }
    }
}

// ---- k4 ----
__global__ __launch_bounds__(256) void k4(const float* __restrict__ x,
                                          float* __restrict__ out) {
    const int t = threadIdx.x, c = blockIdx.x;
    const int blo = (c * 1024) / DDIM;
    const int bhi = ((c + 1) * 1024 - 1) / DDIM;
    __shared__ float wsum[8];
    __shared__ float invs[2];
    {
        int myb = (t < 128) ? blo : bhi;
        float s = g_psum[myb * 128 + (t & 127)];
        for (int o = 16; o; o >>= 1) s += __shfl_xor_sync(0xffffffffu, s, o);
        if ((t & 31) == 0) wsum[t >> 5] = s;
    }
    __syncthreads();
    if (t == 0)   invs[0] = 1.f / (wsum[0] + wsum[1] + wsum[2] + wsum[3]);
    if (t == 128) invs[1] = 1.f / (wsum[4] + wsum[5] + wsum[6] + wsum[7]);
    __syncthreads();

    const float at = g_c[0], bt2 = g_c[1];
    int i = (c * 256 + t) * 4;
    int b = i / DDIM;
    int d = i - b * DDIM;
    float inv = (b == blo) ? invs[0] : invs[1];
    float4 m0 = *(const float4*)(g_mp + (size_t)b * DDIM + d);
    float4 m1 = *(const float4*)(g_mp + (size_t)(16 + b) * DDIM + d);
    float4 m2 = *(const float4*)(g_mp + (size_t)(32 + b) * DDIM + d);
    float4 m3 = *(const float4*)(g_mp + (size_t)(48 + b) * DDIM + d);
    float4 xv = *(const float4*)(x + i);
    float sc = at * inv / bt2;
    float4 o;
    o.x = sc * (m0.x + m1.x + m2.x + m3.x) - xv.x / bt2;
    o.y = sc * (m0.y + m1.y + m2.y + m3.y) - xv.y / bt2;
    o.z = sc * (m0.z + m1.z + m2.z + m3.z) - xv.z / bt2;
    o.w = sc * (m0.w + m1.w + m2.w + m3.w) - xv.w / bt2;
    *(float4*)(out + i) = o;
}

extern "C" void kernel_launch(void* const* d_in, const int* in_sizes, int n_in,
                              void* d_out, int out_size) {
    const float* x    = (const float*)d_in[0];
    const float* img  = (const float*)d_in[1];
    const float* sval = (const float*)d_in[2];
    float* out = (float*)d_out;

    kconst<<<1, 32>>>(sval);       // 0
    ktr<<<96, 256>>>(x, 0);        // 1
    ktr<<<96, 256>>>(x, 24576);    // 2
    k1<<<316, 256>>>(img);         // 3  <- capture lands on NEW k1
    sm<<<128, 256>>>();            // 4
    k3<<<384, 256>>>(img);         // 5
    k4<<<48, 256>>>(x, out);       // 6
}